// round 14
// baseline (speedup 1.0000x reference)
#include <cuda_runtime.h>
#include <cuda_fp16.h>
#include <cstdint>

typedef unsigned long long ull;

#define SCALE 0.17677669529663687f   // 32^-0.5

// ---------------- device scratch ----------------
// g_KV: per window (2048) 65536 B: K-hi 32KB | V-hi 32KB (fp16)
// each 32KB block: [64 rows m][256 dims d], blocked SW128 (atom 8x64)
__device__ __align__(128) uint8_t g_KV[2048ULL * 65536];
__device__ __align__(128) float g_q [8 * 64 * 32];       // [(h*64+n)*32+e], * SCALE
__device__ __align__(128) float g_biasF[32768];          // C-frag-ordered bias
__device__ __align__(128) uint4 g_qfrag[128 * 32];       // A-frag-ordered q (hi/lo fp16)
// Weight stages: fp16 HI ONLY. 32KB stage = 128 cols x 128 k. kv: 8 stages, proj: 4.
__device__ __align__(128) __half g_kvw_blk[131072];
__device__ __align__(128) __half g_pw_blk [65536];

// ---------------- helpers ----------------
__device__ __forceinline__ uint32_t smem_u32(const void* p) {
    uint32_t a;
    asm("{ .reg .u64 t; cvta.to.shared.u64 t, %1; cvt.u32.u64 %0, t; }" : "=r"(a) : "l"(p));
    return a;
}

// 128-row blocked SW128 (GEMM A tile + weight stages)
__device__ __forceinline__ uint32_t a_sw_off(int m, int kk) {
    uint32_t off = ((uint32_t)(kk >> 6) * 16 + (m >> 3)) * 1024 + (m & 7) * 128 + (kk & 63) * 2;
    return off ^ ((off >> 3) & 0x70);
}
// 64-row blocked SW128 (per-window K/V/O blocks)
__device__ __forceinline__ uint32_t kv_off(int m, int d) {
    uint32_t off = ((uint32_t)(d >> 6) * 8 + (m >> 3)) * 1024 + (m & 7) * 128 + (d & 63) * 2;
    return off ^ ((off >> 3) & 0x70);
}

// split fp32 pair -> fp16x2 hi (returned) + fp16x2 lo
__device__ __forceinline__ uint32_t split2h(float a, float b, uint32_t& lo) {
    __half2 h = __floats2half2_rn(a, b);
    float2 hf = __half22float2(h);
    __half2 l = __floats2half2_rn(a - hf.x, b - hf.y);
    lo = *(uint32_t*)&l;
    return *(uint32_t*)&h;
}
__device__ __forceinline__ uint32_t pack2h(float a, float b) {
    __half2 h = __floats2half2_rn(a, b);
    return *(uint32_t*)&h;
}

__device__ __forceinline__ void ldsm_x4(uint32_t* r, uint32_t addr) {
    asm volatile("ldmatrix.sync.aligned.m8n8.x4.shared.b16 {%0,%1,%2,%3}, [%4];"
        : "=r"(r[0]), "=r"(r[1]), "=r"(r[2]), "=r"(r[3]) : "r"(addr));
}
__device__ __forceinline__ void ldsm_x4_t(uint32_t* r, uint32_t addr) {
    asm volatile("ldmatrix.sync.aligned.m8n8.x4.trans.shared.b16 {%0,%1,%2,%3}, [%4];"
        : "=r"(r[0]), "=r"(r[1]), "=r"(r[2]), "=r"(r[3]) : "r"(addr));
}
__device__ __forceinline__ void mma16816(float* c, const uint32_t* a, const uint32_t* b) {
    asm volatile(
        "mma.sync.aligned.m16n8k16.row.col.f32.f16.f16.f32 "
        "{%0,%1,%2,%3}, {%4,%5,%6,%7}, {%8,%9}, {%0,%1,%2,%3};"
        : "+f"(c[0]), "+f"(c[1]), "+f"(c[2]), "+f"(c[3])
        : "r"(a[0]), "r"(a[1]), "r"(a[2]), "r"(a[3]), "r"(b[0]), "r"(b[1]));
}

// ---------------- setup 1: q, bias(frag order), weight stages (fp16 hi) ----------------
__global__ void setup_kernel(const float* __restrict__ emb,
                             const float* __restrict__ rpb,
                             const float* __restrict__ q_w,
                             const float* __restrict__ q_b,
                             const float* __restrict__ kv_w,
                             const float* __restrict__ proj_w) {
    int gid = blockIdx.x * blockDim.x + threadIdx.x;   // < 245760
    if (gid < 16384) {
        int e = gid & 31; int hn = gid >> 5;
        int h = hn >> 6, n = hn & 63;
        int d = h * 32 + e;
        const float* er = emb + n * 256;
        const float* wr = q_w + d * 256;
        float acc = q_b[d];
        #pragma unroll 4
        for (int c = 0; c < 256; c++) acc = fmaf(er[c], wr[c], acc);
        g_q[gid] = acc * SCALE;
    } else if (gid < 49152) {
        // bias in C-fragment order
        int t = gid - 16384;
        int r = t & 3, lane = (t >> 2) & 31, nt = (t >> 7) & 7;
        int mt = (t >> 10) & 1, s = (t >> 11) & 1, h = t >> 12;
        int n = s * 32 + mt * 16 + (lane >> 2) + ((r >> 1) << 3);
        int m = nt * 8 + ((lane & 3) << 1) + (r & 1);
        int r0 = (n >> 3) - (m >> 3) + 7;
        int r1 = (n & 7) - (m & 7) + 7;
        g_biasF[t] = rpb[(r0 * 15 + r1) * 8 + h];
    } else if (gid < 180224) {
        // kv_w fp16 hi: 512 rows x 256 k -> 8 stages of 32KB
        int t = gid - 49152;             // n*256 + kk, n < 512
        int n = t >> 8, kk = t & 255;
        int stage = (n >> 7) * 2 + (kk >> 7);
        uint32_t off = (uint32_t)stage * 32768 + a_sw_off(n & 127, kk & 127);
        g_kvw_blk[off >> 1] = __float2half(kv_w[n * 256 + kk]);
    } else {
        // proj_w fp16 hi: 256 rows x 256 k -> 4 stages
        int t = gid - 180224;            // n*256 + kk, n < 256
        int n = t >> 8, kk = t & 255;
        int stage = (n >> 7) * 2 + (kk >> 7);
        uint32_t off = (uint32_t)stage * 32768 + a_sw_off(n & 127, kk & 127);
        g_pw_blk[off >> 1] = __float2half(proj_w[n * 256 + kk]);
    }
}

// ---------------- setup 2: q A-fragments (128 slots: h,s,mt,kt,prec) ----------------
__global__ void setup2_kernel() {
    int t = blockIdx.x * blockDim.x + threadIdx.x;   // 4096
    int lane = t & 31, slot = t >> 5;                // slot 0..127
    int prec = slot & 1, kt = (slot >> 1) & 1, mt = (slot >> 2) & 1;
    int s = (slot >> 3) & 1, h = slot >> 4;
    uint32_t rr[4];
    #pragma unroll
    for (int r = 0; r < 4; r++) {
        int n = s * 32 + mt * 16 + (lane >> 2) + ((r & 1) << 3);
        int k = kt * 16 + ((lane & 3) << 1) + ((r >> 1) << 3);
        float q0 = g_q[(h * 64 + n) * 32 + k];
        float q1 = g_q[(h * 64 + n) * 32 + k + 1];
        uint32_t lo;
        uint32_t hi = split2h(q0, q1, lo);
        rr[r] = prec ? lo : hi;
    }
    g_qfrag[slot * 32 + lane] = make_uint4(rr[0], rr[1], rr[2], rr[3]);
}

// ---------------- kv epilogue store: fp32 pair -> fp16 hi into window blocks ----------------
__device__ __forceinline__ void store2_kv(int r, int col, float a, float b) {
    const int w = r >> 6, m = r & 63;
    const int isV = col >= 256;
    const int d = col - (isV ? 256 : 0);
    uint8_t* base = g_KV + (size_t)w * 65536 + (isV ? 32768 : 0);
    *(uint32_t*)(base + kv_off(m, d)) = pack2h(a, b);
}

// ---------------- mma.sync fp16 GEMM (kv): C = Ah @ Wh^T + bias (1 term) ----------------
__global__ void __launch_bounds__(512, 1)
gemm_kernel(const float* __restrict__ xsrc,
            const float* __restrict__ bias) {
    extern __shared__ char gsm[];
    const uint32_t sraw = smem_u32(gsm);
    const uint32_t sA = (sraw + 1023) & ~1023u;    // 64KB A tile (fp16 hi)
    const uint32_t sB = sA + 65536;                // 4 x 32KB ring

    const int tid = threadIdx.x;
    const int wid = tid >> 5;
    const int lid = tid & 31;
    const int r0  = blockIdx.x * 128;
    const int NST = 8;

    char* Ab = gsm + (sA - sraw);

    auto issue_copy = [&](int j) {
        uint32_t dst = sB + (uint32_t)(j & 3) * 32768 + (uint32_t)tid * 64;
        const char* src = (const char*)g_kvw_blk + (size_t)j * 32768 + (size_t)tid * 64;
        #pragma unroll
        for (int q = 0; q < 4; q++)
            asm volatile("cp.async.cg.shared.global [%0], [%1], 16;"
                         :: "r"(dst + q * 16), "l"(src + q * 16));
        asm volatile("cp.async.commit_group;" ::: "memory");
    };

    issue_copy(0); issue_copy(1); issue_copy(2);

    // ---- build A tile: fp32 -> fp16 hi only ----
    #pragma unroll 4
    for (int it = 0; it < 32; it++) {
        int idx = tid + it * 512;
        int m = idx >> 7, p = idx & 127, c = p * 2;
        int r = r0 + m;
        int b = r >> 14, i = (r >> 10) & 15, j = (r >> 6) & 15, n = r & 63;
        const float* rowp = xsrc + ((size_t)b << 22) + ((size_t)i << 18)
             + ((size_t)(n >> 3) << 15) + ((size_t)j << 11) + ((size_t)(n & 7) << 8);
        float2 f = *(const float2*)(rowp + c);
        *(uint32_t*)(Ab + a_sw_off(m, c)) = pack2h(f.x, f.y);
    }

    const int m0w = (wid >> 2) * 32;
    const int n0w = (wid & 3) * 32;
    const int lrow = lid & 7;
    const int quad = lid >> 3;
    const int mA0 = m0w + lrow + (quad & 1) * 8;
    const int mA1 = mA0 + 16;
    const uint32_t aoff0 = ((uint32_t)(mA0 >> 3) << 10) + ((uint32_t)(mA0 & 7) << 7);
    const uint32_t aoff1 = ((uint32_t)(mA1 >> 3) << 10) + ((uint32_t)(mA1 & 7) << 7);
    const uint32_t xorA  = (uint32_t)(mA0 & 7) << 4;
    const int kqa = (quad >> 1) * 8;
    const int nB0 = n0w + lrow + (quad >> 1) * 8;
    const uint32_t boff0 = ((uint32_t)(nB0 >> 3) << 10) + ((uint32_t)(nB0 & 7) << 7);
    const uint32_t boff1 = boff0 + 2048;
    const uint32_t xorB  = (uint32_t)(nB0 & 7) << 4;
    const int kqb = (quad & 1) * 8;

    auto ldA = [&](int ak, uint32_t* d0, uint32_t* d1) {
        uint32_t kp = (((uint32_t)(ak >> 6)) << 14) | (((uint32_t)(ak & 63)) << 1);
        ldsm_x4(d0, sA + aoff0 + (kp ^ xorA));
        ldsm_x4(d1, sA + aoff1 + (kp ^ xorA));
    };
    auto ldB2 = [&](uint32_t slot, int kl, uint32_t* d0, uint32_t* d1) {
        uint32_t kp = (((uint32_t)(kl >> 6)) << 14) | (((uint32_t)(kl & 63)) << 1);
        ldsm_x4(d0, slot + boff0 + (kp ^ xorB));
        ldsm_x4(d1, slot + boff1 + (kp ^ xorB));
    };

    float c[2][4][4];
    #pragma unroll
    for (int mt = 0; mt < 2; mt++)
        #pragma unroll
        for (int nt = 0; nt < 4; nt++)
            #pragma unroll
            for (int i = 0; i < 4; i++) c[mt][nt][i] = 0.f;

    uint32_t fh0[2][4], fh1[2][4], fb0[2][4], fb1[2][4];

    auto mma8 = [&](uint32_t* a0, uint32_t* a1, uint32_t* b0, uint32_t* b1) {
        mma16816(c[0][0], a0, b0);
        mma16816(c[0][1], a0, b0 + 2);
        mma16816(c[0][2], a0, b1);
        mma16816(c[0][3], a0, b1 + 2);
        mma16816(c[1][0], a1, b0);
        mma16816(c[1][1], a1, b0 + 2);
        mma16816(c[1][2], a1, b1);
        mma16816(c[1][3], a1, b1 + 2);
    };

    for (int i = 0; i < NST; i++) {
        asm volatile("cp.async.wait_group 2;" ::: "memory");
        __syncthreads();
        if (i + 3 < NST) issue_copy(i + 3);

        const uint32_t slot = sB + (uint32_t)(i & 3) * 32768;
        const int kb = (i & 1) * 128;

        ldA(kb + kqa, fh0[0], fh1[0]);
        ldB2(slot, kqb, fb0[0], fb1[0]);
        #pragma unroll
        for (int st = 0; st < 8; st++) {
            const int cb = st & 1, nb = cb ^ 1;
            if (st < 7) {
                ldA(kb + (st + 1) * 16 + kqa, fh0[nb], fh1[nb]);
                ldB2(slot, (st + 1) * 16 + kqb, fb0[nb], fb1[nb]);
            }
            mma8(fh0[cb], fh1[cb], fb0[cb], fb1[cb]);
        }

        if (i & 1) {
            const int colb = (i >> 1) * 128 + n0w;
            #pragma unroll
            for (int nt = 0; nt < 4; nt++) {
                const int col = colb + nt * 8 + 2 * (lid & 3);
                const float2 bv = *(const float2*)(bias + col);
                #pragma unroll
                for (int mt = 0; mt < 2; mt++) {
                    const int rlo = r0 + m0w + mt * 16 + (lid >> 2);
                    store2_kv(rlo,     col, c[mt][nt][0] + bv.x, c[mt][nt][1] + bv.y);
                    store2_kv(rlo + 8, col, c[mt][nt][2] + bv.x, c[mt][nt][3] + bv.y);
                }
            }
            #pragma unroll
            for (int mt = 0; mt < 2; mt++)
                #pragma unroll
                for (int nt = 0; nt < 4; nt++)
                    #pragma unroll
                    for (int k2 = 0; k2 < 4; k2++) c[mt][nt][k2] = 0.f;
        }
    }
}

// ------- fused attention + proj: 1 CTA per 2 windows, proj weights resident --------
__global__ void __launch_bounds__(512, 1)
attn_kernel(const float* __restrict__ proj_b, float* __restrict__ out) {
    extern __shared__ char asmem[];
    const uint32_t sraw = smem_u32(asmem);
    const uint32_t sKV = (sraw + 1023) & ~1023u;   // 64KB: K-hi | V-hi (per window)
    const uint32_t sO  = sKV + 65536;              // 32KB: O-hi stage
    const uint32_t sP  = sO + 32768;               // 128KB proj weights (resident)
    const int tid = threadIdx.x;

    auto issue_kv = [&](int win) {
        const uint8_t* src = g_KV + (size_t)win * 65536;
        #pragma unroll
        for (int t = 0; t < 8; t++) {
            uint32_t o = (uint32_t)(tid + t * 512) * 16;
            asm volatile("cp.async.cg.shared.global [%0], [%1], 16;"
                         :: "r"(sKV + o), "l"(src + o));
        }
        asm volatile("cp.async.commit_group;" ::: "memory");
    };

    // G0: KV(win0); G1+G2: proj weights 128KB
    issue_kv(blockIdx.x * 2);
    #pragma unroll
    for (int t = 0; t < 8; t++) {
        uint32_t o = (uint32_t)(tid + t * 512) * 16;
        asm volatile("cp.async.cg.shared.global [%0], [%1], 16;"
                     :: "r"(sP + o), "l"((const char*)g_pw_blk + o));
    }
    asm volatile("cp.async.commit_group;" ::: "memory");
    #pragma unroll
    for (int t = 8; t < 16; t++) {
        uint32_t o = (uint32_t)(tid + t * 512) * 16;
        asm volatile("cp.async.cg.shared.global [%0], [%1], 16;"
                     :: "r"(sP + o), "l"((const char*)g_pw_blk + o));
    }
    asm volatile("cp.async.commit_group;" ::: "memory");

    const int wid = tid >> 5, lid = tid & 31;
    const int h = wid >> 1, s = wid & 1;
    const int lrow = lid & 7, grp = lid >> 3;
    const int q2 = (lid & 3) * 2, r4 = lid >> 2;

    // proj geometry (fixed per thread)
    const int mw = wid >> 2, nw = wid & 3;          // warp tile 16 rows x 64 cols
    const int arow = mw * 16 + lrow + (grp & 1) * 8;
    const int pkqa = (grp >> 1) * 8;
    const int pkqb = (grp & 1) * 8;
    int nrow[4];
    #pragma unroll
    for (int t = 0; t < 4; t++) nrow[t] = nw * 64 + t * 16 + lrow + (grp >> 1) * 8;
    const uint32_t sPw = sP + (uint32_t)(nw >> 1) * 65536;

    #pragma unroll 1
    for (int w = 0; w < 2; w++) {
        const int win = blockIdx.x * 2 + w;

        // wait for this window's KV (w0: G1,G2 may pend; w1: all done)
        if (w == 0) asm volatile("cp.async.wait_group 2;" ::: "memory");
        else        asm volatile("cp.async.wait_group 0;" ::: "memory");
        __syncthreads();

        // bias -> accumulators (C-frag order), q fragments (A-frag order)
        float sa[2][8][4];
        const float4* bf = (const float4*)g_biasF;
        #pragma unroll
        for (int mt = 0; mt < 2; mt++)
            #pragma unroll
            for (int nt = 0; nt < 8; nt++) {
                float4 b = bf[((((h * 2 + s) * 2 + mt) * 8) + nt) * 32 + lid];
                sa[mt][nt][0] = b.x; sa[mt][nt][1] = b.y;
                sa[mt][nt][2] = b.z; sa[mt][nt][3] = b.w;
            }
        uint4 qh[2][2], ql[2][2];
        #pragma unroll
        for (int mt = 0; mt < 2; mt++)
            #pragma unroll
            for (int kt = 0; kt < 2; kt++) {
                int sb = (((h * 2 + s) * 2 + mt) * 2 + kt) * 2;
                qh[mt][kt] = g_qfrag[sb * 32 + lid];
                ql[mt][kt] = g_qfrag[(sb + 1) * 32 + lid];
            }

        // ---- S = (Qh+Ql)@Kh  (bias preloaded) ----
        #pragma unroll
        for (int kt = 0; kt < 2; kt++) {
            const int dcol = h * 32 + kt * 16 + (grp & 1) * 8;
            #pragma unroll
            for (int ntp = 0; ntp < 4; ntp++) {
                const int mrow = ntp * 16 + lrow + (grp >> 1) * 8;
                uint32_t a = sKV + kv_off(mrow, dcol);
                uint32_t bh[4];
                ldsm_x4(bh, a);
                mma16816(sa[0][2*ntp],   (const uint32_t*)&qh[0][kt], bh);
                mma16816(sa[0][2*ntp+1], (const uint32_t*)&qh[0][kt], bh + 2);
                mma16816(sa[1][2*ntp],   (const uint32_t*)&qh[1][kt], bh);
                mma16816(sa[1][2*ntp+1], (const uint32_t*)&qh[1][kt], bh + 2);
                mma16816(sa[0][2*ntp],   (const uint32_t*)&ql[0][kt], bh);
                mma16816(sa[0][2*ntp+1], (const uint32_t*)&ql[0][kt], bh + 2);
                mma16816(sa[1][2*ntp],   (const uint32_t*)&ql[1][kt], bh);
                mma16816(sa[1][2*ntp+1], (const uint32_t*)&ql[1][kt], bh + 2);
            }
        }

        // ---- softmax ----
        float rinv[2][2];
        #pragma unroll
        for (int mt = 0; mt < 2; mt++)
            #pragma unroll
            for (int rh = 0; rh < 2; rh++) {
                float mx = -1e30f;
                #pragma unroll
                for (int nt = 0; nt < 8; nt++)
                    mx = fmaxf(mx, fmaxf(sa[mt][nt][rh*2], sa[mt][nt][rh*2+1]));
                mx = fmaxf(mx, __shfl_xor_sync(0xffffffffu, mx, 1));
                mx = fmaxf(mx, __shfl_xor_sync(0xffffffffu, mx, 2));
                float ls = 0.f;
                #pragma unroll
                for (int nt = 0; nt < 8; nt++) {
                    float p0 = __expf(sa[mt][nt][rh*2]   - mx);
                    float p1 = __expf(sa[mt][nt][rh*2+1] - mx);
                    sa[mt][nt][rh*2] = p0; sa[mt][nt][rh*2+1] = p1;
                    ls += p0 + p1;
                }
                ls += __shfl_xor_sync(0xffffffffu, ls, 1);
                ls += __shfl_xor_sync(0xffffffffu, ls, 2);
                rinv[mt][rh] = 1.f / ls;
            }

        // ---- O = (Ph+Pl)@Vh ----
        float oa[2][4][4];
        #pragma unroll
        for (int mt = 0; mt < 2; mt++)
            #pragma unroll
            for (int nt = 0; nt < 4; nt++)
                #pragma unroll
                for (int i = 0; i < 4; i++) oa[mt][nt][i] = 0.f;

        #pragma unroll
        for (int j = 0; j < 4; j++) {
            uint32_t Ph[2][4], Pl[2][4];
            #pragma unroll
            for (int mt = 0; mt < 2; mt++) {
                Ph[mt][0] = split2h(sa[mt][2*j][0],   sa[mt][2*j][1],   Pl[mt][0]);
                Ph[mt][1] = split2h(sa[mt][2*j][2],   sa[mt][2*j][3],   Pl[mt][1]);
                Ph[mt][2] = split2h(sa[mt][2*j+1][0], sa[mt][2*j+1][1], Pl[mt][2]);
                Ph[mt][3] = split2h(sa[mt][2*j+1][2], sa[mt][2*j+1][3], Pl[mt][3]);
            }
            #pragma unroll
            for (int ep = 0; ep < 2; ep++) {
                const int mrow = j * 16 + lrow + (grp & 1) * 8;
                const int ecol = h * 32 + ep * 16 + (grp >> 1) * 8;
                uint32_t va = sKV + 32768 + kv_off(mrow, ecol);
                uint32_t vh[4];
                ldsm_x4_t(vh, va);
                #pragma unroll
                for (int mt = 0; mt < 2; mt++) {
                    mma16816(oa[mt][2*ep],   Ph[mt], vh);
                    mma16816(oa[mt][2*ep+1], Ph[mt], vh + 2);
                    mma16816(oa[mt][2*ep],   Pl[mt], vh);
                    mma16816(oa[mt][2*ep+1], Pl[mt], vh + 2);
                }
            }
        }

        // ---- KV reads done: prefetch next window's KV under O-stage + proj ----
        __syncthreads();
        if (w == 0) issue_kv(win + 1);                       // G3

        // ---- stage O (scaled) into sO as fp16 hi, 64-row SW128 layout ----
        char* sm = asmem + (sO - sraw);
        #pragma unroll
        for (int mt = 0; mt < 2; mt++)
            #pragma unroll
            for (int rh = 0; rh < 2; rh++) {
                const int n = s * 32 + mt * 16 + r4 + rh * 8;
                const float sc = rinv[mt][rh];
                #pragma unroll
                for (int nt = 0; nt < 4; nt++) {
                    const int col = h * 32 + nt * 8 + q2;
                    *(uint32_t*)(sm + kv_off(n, col)) =
                        pack2h(oa[mt][nt][rh*2] * sc, oa[mt][nt][rh*2+1] * sc);
                }
            }
        if (w == 0) asm volatile("cp.async.wait_group 1;" ::: "memory");  // P done
        __syncthreads();

        // ---- proj: C[64x256] = Oh @ PWh^T + proj_b (1 term, full unroll) ----
        float pc[8][4];
        #pragma unroll
        for (int nt = 0; nt < 8; nt++)
            #pragma unroll
            for (int i = 0; i < 4; i++) pc[nt][i] = 0.f;

        #pragma unroll
        for (int ks = 0; ks < 16; ks++) {
            const int k = ks * 16;
            uint32_t ah[4], bb[4][4];
            ldsm_x4(ah, sO + kv_off(arow, k + pkqa));
            #pragma unroll
            for (int t = 0; t < 4; t++) {
                uint32_t ba = sPw + (uint32_t)((k + pkqb) >> 7) * 32768
                            + a_sw_off(nrow[t] & 127, (k + pkqb) & 127);
                ldsm_x4(bb[t], ba);
            }
            #pragma unroll
            for (int t = 0; t < 4; t++) {
                mma16816(pc[2*t],   ah, bb[t]);
                mma16816(pc[2*t+1], ah, bb[t] + 2);
            }
        }

        // ---- epilogue: bias + store out ----
        float* obase = out + (size_t)win * 64 * 256;
        #pragma unroll
        for (int nt = 0; nt < 8; nt++) {
            const int col = nw * 64 + nt * 8 + q2;
            const float2 bv = *(const float2*)(proj_b + col);
            const int rlo = mw * 16 + r4;
            *(float2*)(obase + (size_t)rlo * 256 + col) =
                make_float2(pc[nt][0] + bv.x, pc[nt][1] + bv.y);
            *(float2*)(obase + (size_t)(rlo + 8) * 256 + col) =
                make_float2(pc[nt][2] + bv.x, pc[nt][3] + bv.y);
        }
        __syncthreads();   // proj reads of sO done before next window reuses buffers
    }
}

// ---------------- launcher ----------------
extern "C" void kernel_launch(void* const* d_in, const int* in_sizes, int n_in,
                              void* d_out, int out_size) {
    const float* x      = (const float*)d_in[0];
    const float* emb    = (const float*)d_in[1];
    const float* rpb    = (const float*)d_in[2];
    const float* q_w    = (const float*)d_in[3];
    const float* q_b    = (const float*)d_in[4];
    const float* kv_w   = (const float*)d_in[5];
    const float* kv_b   = (const float*)d_in[6];
    const float* proj_w = (const float*)d_in[7];
    const float* proj_b = (const float*)d_in[8];
    float* out = (float*)d_out;
    (void)in_sizes; (void)n_in; (void)out_size;

    const int GSM = 1024 + 65536 + 131072;           // 197632: pad + A + 4x32KB ring
    const int ASM = 1024 + 65536 + 32768 + 131072;   // 230400: pad + KV + O + P

    cudaFuncSetAttribute(gemm_kernel,
                         cudaFuncAttributeMaxDynamicSharedMemorySize, GSM);
    cudaFuncSetAttribute(attn_kernel,
                         cudaFuncAttributeMaxDynamicSharedMemorySize, ASM);

    setup_kernel<<<480, 512>>>(emb, rpb, q_w, q_b, kv_w, proj_w);
    setup2_kernel<<<8, 512>>>();
    gemm_kernel<<<1024, 512, GSM>>>(x, kv_b);
    attn_kernel<<<1024, 512, ASM>>>(proj_b, out);
}

// round 15
// speedup vs baseline: 1.0420x; 1.0420x over previous
#include <cuda_runtime.h>
#include <cuda_fp16.h>
#include <cstdint>

typedef unsigned long long ull;

#define SCALE 0.17677669529663687f   // 32^-0.5

// ---------------- device scratch ----------------
// g_KV: per window (2048) 65536 B: K-hi 32KB | V-hi 32KB (fp16)
// each 32KB block: [64 rows m][256 dims d], blocked SW128 (atom 8x64)
__device__ __align__(128) uint8_t g_KV[2048ULL * 65536];
__device__ __align__(128) float g_q [8 * 64 * 32];       // [(h*64+n)*32+e], * SCALE
__device__ __align__(128) float g_biasF[32768];          // C-frag-ordered bias
__device__ __align__(128) uint4 g_qfrag[128 * 32];       // A-frag-ordered q (hi/lo fp16)
// Weight stages: fp16 HI ONLY. 32KB stage = 128 cols x 128 k. kv: 8 stages, proj: 4.
__device__ __align__(128) __half g_kvw_blk[131072];
__device__ __align__(128) __half g_pw_blk [65536];

// ---------------- helpers ----------------
__device__ __forceinline__ uint32_t smem_u32(const void* p) {
    uint32_t a;
    asm("{ .reg .u64 t; cvta.to.shared.u64 t, %1; cvt.u32.u64 %0, t; }" : "=r"(a) : "l"(p));
    return a;
}

// 128-row blocked SW128 (GEMM A tile + weight stages)
__device__ __forceinline__ uint32_t a_sw_off(int m, int kk) {
    uint32_t off = ((uint32_t)(kk >> 6) * 16 + (m >> 3)) * 1024 + (m & 7) * 128 + (kk & 63) * 2;
    return off ^ ((off >> 3) & 0x70);
}
// 64-row blocked SW128 (per-window K/V/O blocks)
__device__ __forceinline__ uint32_t kv_off(int m, int d) {
    uint32_t off = ((uint32_t)(d >> 6) * 8 + (m >> 3)) * 1024 + (m & 7) * 128 + (d & 63) * 2;
    return off ^ ((off >> 3) & 0x70);
}

// split fp32 pair -> fp16x2 hi (returned) + fp16x2 lo
__device__ __forceinline__ uint32_t split2h(float a, float b, uint32_t& lo) {
    __half2 h = __floats2half2_rn(a, b);
    float2 hf = __half22float2(h);
    __half2 l = __floats2half2_rn(a - hf.x, b - hf.y);
    lo = *(uint32_t*)&l;
    return *(uint32_t*)&h;
}
__device__ __forceinline__ uint32_t pack2h(float a, float b) {
    __half2 h = __floats2half2_rn(a, b);
    return *(uint32_t*)&h;
}

__device__ __forceinline__ void ldsm_x4(uint32_t* r, uint32_t addr) {
    asm volatile("ldmatrix.sync.aligned.m8n8.x4.shared.b16 {%0,%1,%2,%3}, [%4];"
        : "=r"(r[0]), "=r"(r[1]), "=r"(r[2]), "=r"(r[3]) : "r"(addr));
}
__device__ __forceinline__ void ldsm_x4_t(uint32_t* r, uint32_t addr) {
    asm volatile("ldmatrix.sync.aligned.m8n8.x4.trans.shared.b16 {%0,%1,%2,%3}, [%4];"
        : "=r"(r[0]), "=r"(r[1]), "=r"(r[2]), "=r"(r[3]) : "r"(addr));
}
__device__ __forceinline__ void mma16816(float* c, const uint32_t* a, const uint32_t* b) {
    asm volatile(
        "mma.sync.aligned.m16n8k16.row.col.f32.f16.f16.f32 "
        "{%0,%1,%2,%3}, {%4,%5,%6,%7}, {%8,%9}, {%0,%1,%2,%3};"
        : "+f"(c[0]), "+f"(c[1]), "+f"(c[2]), "+f"(c[3])
        : "r"(a[0]), "r"(a[1]), "r"(a[2]), "r"(a[3]), "r"(b[0]), "r"(b[1]));
}

// ---------------- setup 1: q, bias(frag order), weight stages (fp16 hi) ----------------
__global__ void setup_kernel(const float* __restrict__ emb,
                             const float* __restrict__ rpb,
                             const float* __restrict__ q_w,
                             const float* __restrict__ q_b,
                             const float* __restrict__ kv_w,
                             const float* __restrict__ proj_w) {
    int gid = blockIdx.x * blockDim.x + threadIdx.x;   // < 245760
    if (gid < 16384) {
        int e = gid & 31; int hn = gid >> 5;
        int h = hn >> 6, n = hn & 63;
        int d = h * 32 + e;
        const float* er = emb + n * 256;
        const float* wr = q_w + d * 256;
        float acc = q_b[d];
        #pragma unroll 4
        for (int c = 0; c < 256; c++) acc = fmaf(er[c], wr[c], acc);
        g_q[gid] = acc * SCALE;
    } else if (gid < 49152) {
        // bias in C-fragment order
        int t = gid - 16384;
        int r = t & 3, lane = (t >> 2) & 31, nt = (t >> 7) & 7;
        int mt = (t >> 10) & 1, s = (t >> 11) & 1, h = t >> 12;
        int n = s * 32 + mt * 16 + (lane >> 2) + ((r >> 1) << 3);
        int m = nt * 8 + ((lane & 3) << 1) + (r & 1);
        int r0 = (n >> 3) - (m >> 3) + 7;
        int r1 = (n & 7) - (m & 7) + 7;
        g_biasF[t] = rpb[(r0 * 15 + r1) * 8 + h];
    } else if (gid < 180224) {
        // kv_w fp16 hi: 512 rows x 256 k -> 8 stages of 32KB
        int t = gid - 49152;             // n*256 + kk, n < 512
        int n = t >> 8, kk = t & 255;
        int stage = (n >> 7) * 2 + (kk >> 7);
        uint32_t off = (uint32_t)stage * 32768 + a_sw_off(n & 127, kk & 127);
        g_kvw_blk[off >> 1] = __float2half(kv_w[n * 256 + kk]);
    } else {
        // proj_w fp16 hi: 256 rows x 256 k -> 4 stages
        int t = gid - 180224;            // n*256 + kk, n < 256
        int n = t >> 8, kk = t & 255;
        int stage = (n >> 7) * 2 + (kk >> 7);
        uint32_t off = (uint32_t)stage * 32768 + a_sw_off(n & 127, kk & 127);
        g_pw_blk[off >> 1] = __float2half(proj_w[n * 256 + kk]);
    }
}

// ---------------- setup 2: q A-fragments (128 slots: h,s,mt,kt,prec) ----------------
__global__ void setup2_kernel() {
    int t = blockIdx.x * blockDim.x + threadIdx.x;   // 4096
    int lane = t & 31, slot = t >> 5;                // slot 0..127
    int prec = slot & 1, kt = (slot >> 1) & 1, mt = (slot >> 2) & 1;
    int s = (slot >> 3) & 1, h = slot >> 4;
    uint32_t rr[4];
    #pragma unroll
    for (int r = 0; r < 4; r++) {
        int n = s * 32 + mt * 16 + (lane >> 2) + ((r & 1) << 3);
        int k = kt * 16 + ((lane & 3) << 1) + ((r >> 1) << 3);
        float q0 = g_q[(h * 64 + n) * 32 + k];
        float q1 = g_q[(h * 64 + n) * 32 + k + 1];
        uint32_t lo;
        uint32_t hi = split2h(q0, q1, lo);
        rr[r] = prec ? lo : hi;
    }
    g_qfrag[slot * 32 + lane] = make_uint4(rr[0], rr[1], rr[2], rr[3]);
}

// ---------------- kv epilogue store: fp32 pair -> fp16 hi into window blocks ----------------
__device__ __forceinline__ void store2_kv(int r, int col, float a, float b) {
    const int w = r >> 6, m = r & 63;
    const int isV = col >= 256;
    const int d = col - (isV ? 256 : 0);
    uint8_t* base = g_KV + (size_t)w * 65536 + (isV ? 32768 : 0);
    *(uint32_t*)(base + kv_off(m, d)) = pack2h(a, b);
}

// ---------------- mma.sync fp16 GEMM (kv): C = Ah @ Wh^T + bias (1 term) ----------------
__global__ void __launch_bounds__(512, 1)
gemm_kernel(const float* __restrict__ xsrc,
            const float* __restrict__ bias) {
    extern __shared__ char gsm[];
    const uint32_t sraw = smem_u32(gsm);
    const uint32_t sA = (sraw + 1023) & ~1023u;    // 64KB A tile (fp16 hi)
    const uint32_t sB = sA + 65536;                // 4 x 32KB ring

    const int tid = threadIdx.x;
    const int wid = tid >> 5;
    const int lid = tid & 31;
    const int r0  = blockIdx.x * 128;
    const int NST = 8;

    char* Ab = gsm + (sA - sraw);

    auto issue_copy = [&](int j) {
        uint32_t dst = sB + (uint32_t)(j & 3) * 32768 + (uint32_t)tid * 64;
        const char* src = (const char*)g_kvw_blk + (size_t)j * 32768 + (size_t)tid * 64;
        #pragma unroll
        for (int q = 0; q < 4; q++)
            asm volatile("cp.async.cg.shared.global [%0], [%1], 16;"
                         :: "r"(dst + q * 16), "l"(src + q * 16));
        asm volatile("cp.async.commit_group;" ::: "memory");
    };

    issue_copy(0); issue_copy(1); issue_copy(2);

    // ---- build A tile: fp32 -> fp16 hi only ----
    #pragma unroll 4
    for (int it = 0; it < 32; it++) {
        int idx = tid + it * 512;
        int m = idx >> 7, p = idx & 127, c = p * 2;
        int r = r0 + m;
        int b = r >> 14, i = (r >> 10) & 15, j = (r >> 6) & 15, n = r & 63;
        const float* rowp = xsrc + ((size_t)b << 22) + ((size_t)i << 18)
             + ((size_t)(n >> 3) << 15) + ((size_t)j << 11) + ((size_t)(n & 7) << 8);
        float2 f = *(const float2*)(rowp + c);
        *(uint32_t*)(Ab + a_sw_off(m, c)) = pack2h(f.x, f.y);
    }

    const int m0w = (wid >> 2) * 32;
    const int n0w = (wid & 3) * 32;
    const int lrow = lid & 7;
    const int quad = lid >> 3;
    const int mA0 = m0w + lrow + (quad & 1) * 8;
    const int mA1 = mA0 + 16;
    const uint32_t aoff0 = ((uint32_t)(mA0 >> 3) << 10) + ((uint32_t)(mA0 & 7) << 7);
    const uint32_t aoff1 = ((uint32_t)(mA1 >> 3) << 10) + ((uint32_t)(mA1 & 7) << 7);
    const uint32_t xorA  = (uint32_t)(mA0 & 7) << 4;
    const int kqa = (quad >> 1) * 8;
    const int nB0 = n0w + lrow + (quad >> 1) * 8;
    const uint32_t boff0 = ((uint32_t)(nB0 >> 3) << 10) + ((uint32_t)(nB0 & 7) << 7);
    const uint32_t boff1 = boff0 + 2048;
    const uint32_t xorB  = (uint32_t)(nB0 & 7) << 4;
    const int kqb = (quad & 1) * 8;

    auto ldA = [&](int ak, uint32_t* d0, uint32_t* d1) {
        uint32_t kp = (((uint32_t)(ak >> 6)) << 14) | (((uint32_t)(ak & 63)) << 1);
        ldsm_x4(d0, sA + aoff0 + (kp ^ xorA));
        ldsm_x4(d1, sA + aoff1 + (kp ^ xorA));
    };
    auto ldB2 = [&](uint32_t slot, int kl, uint32_t* d0, uint32_t* d1) {
        uint32_t kp = (((uint32_t)(kl >> 6)) << 14) | (((uint32_t)(kl & 63)) << 1);
        ldsm_x4(d0, slot + boff0 + (kp ^ xorB));
        ldsm_x4(d1, slot + boff1 + (kp ^ xorB));
    };

    float c[2][4][4];
    #pragma unroll
    for (int mt = 0; mt < 2; mt++)
        #pragma unroll
        for (int nt = 0; nt < 4; nt++)
            #pragma unroll
            for (int i = 0; i < 4; i++) c[mt][nt][i] = 0.f;

    uint32_t fh0[2][4], fh1[2][4], fb0[2][4], fb1[2][4];

    auto mma8 = [&](uint32_t* a0, uint32_t* a1, uint32_t* b0, uint32_t* b1) {
        mma16816(c[0][0], a0, b0);
        mma16816(c[0][1], a0, b0 + 2);
        mma16816(c[0][2], a0, b1);
        mma16816(c[0][3], a0, b1 + 2);
        mma16816(c[1][0], a1, b0);
        mma16816(c[1][1], a1, b0 + 2);
        mma16816(c[1][2], a1, b1);
        mma16816(c[1][3], a1, b1 + 2);
    };

    for (int i = 0; i < NST; i++) {
        asm volatile("cp.async.wait_group 2;" ::: "memory");
        __syncthreads();
        if (i + 3 < NST) issue_copy(i + 3);

        const uint32_t slot = sB + (uint32_t)(i & 3) * 32768;
        const int kb = (i & 1) * 128;

        ldA(kb + kqa, fh0[0], fh1[0]);
        ldB2(slot, kqb, fb0[0], fb1[0]);
        #pragma unroll
        for (int st = 0; st < 8; st++) {
            const int cb = st & 1, nb = cb ^ 1;
            if (st < 7) {
                ldA(kb + (st + 1) * 16 + kqa, fh0[nb], fh1[nb]);
                ldB2(slot, (st + 1) * 16 + kqb, fb0[nb], fb1[nb]);
            }
            mma8(fh0[cb], fh1[cb], fb0[cb], fb1[cb]);
        }

        if (i & 1) {
            const int colb = (i >> 1) * 128 + n0w;
            #pragma unroll
            for (int nt = 0; nt < 4; nt++) {
                const int col = colb + nt * 8 + 2 * (lid & 3);
                const float2 bv = *(const float2*)(bias + col);
                #pragma unroll
                for (int mt = 0; mt < 2; mt++) {
                    const int rlo = r0 + m0w + mt * 16 + (lid >> 2);
                    store2_kv(rlo,     col, c[mt][nt][0] + bv.x, c[mt][nt][1] + bv.y);
                    store2_kv(rlo + 8, col, c[mt][nt][2] + bv.x, c[mt][nt][3] + bv.y);
                }
            }
            #pragma unroll
            for (int mt = 0; mt < 2; mt++)
                #pragma unroll
                for (int nt = 0; nt < 4; nt++)
                    #pragma unroll
                    for (int k2 = 0; k2 < 4; k2++) c[mt][nt][k2] = 0.f;
        }
    }
}

// ------- fused attention + proj: 1 CTA per window, writes final out --------
__global__ void __launch_bounds__(512, 1)
attn_kernel(const float* __restrict__ proj_b, float* __restrict__ out) {
    extern __shared__ char asmem[];
    const uint32_t sraw = smem_u32(asmem);
    const uint32_t sKV = (sraw + 1023) & ~1023u;   // 64KB: K-hi | V-hi; later O-hi
    const uint32_t sP  = sKV + 65536;              // 128KB proj weights (4 stages)
    const int tid = threadIdx.x;
    const uint8_t* src = g_KV + (size_t)blockIdx.x * 65536;

    // group0: KV 64KB; group1+2: proj weights 128KB
    #pragma unroll
    for (int t = 0; t < 8; t++) {
        uint32_t o = (uint32_t)(tid + t * 512) * 16;
        asm volatile("cp.async.cg.shared.global [%0], [%1], 16;"
                     :: "r"(sKV + o), "l"(src + o));
    }
    asm volatile("cp.async.commit_group;" ::: "memory");
    #pragma unroll
    for (int t = 0; t < 8; t++) {
        uint32_t o = (uint32_t)(tid + t * 512) * 16;
        asm volatile("cp.async.cg.shared.global [%0], [%1], 16;"
                     :: "r"(sP + o), "l"((const char*)g_pw_blk + o));
    }
    asm volatile("cp.async.commit_group;" ::: "memory");
    #pragma unroll
    for (int t = 8; t < 16; t++) {
        uint32_t o = (uint32_t)(tid + t * 512) * 16;
        asm volatile("cp.async.cg.shared.global [%0], [%1], 16;"
                     :: "r"(sP + o), "l"((const char*)g_pw_blk + o));
    }
    asm volatile("cp.async.commit_group;" ::: "memory");

    const int wid = tid >> 5, lid = tid & 31;
    const int h = wid >> 1, s = wid & 1;
    const int lrow = lid & 7, grp = lid >> 3;

    // bias -> accumulators (C-frag order), q fragments (A-frag order)
    float sa[2][8][4];
    const float4* bf = (const float4*)g_biasF;
    #pragma unroll
    for (int mt = 0; mt < 2; mt++)
        #pragma unroll
        for (int nt = 0; nt < 8; nt++) {
            float4 b = bf[((((h * 2 + s) * 2 + mt) * 8) + nt) * 32 + lid];
            sa[mt][nt][0] = b.x; sa[mt][nt][1] = b.y;
            sa[mt][nt][2] = b.z; sa[mt][nt][3] = b.w;
        }
    uint4 qh[2][2], ql[2][2];
    #pragma unroll
    for (int mt = 0; mt < 2; mt++)
        #pragma unroll
        for (int kt = 0; kt < 2; kt++) {
            int sb = (((h * 2 + s) * 2 + mt) * 2 + kt) * 2;
            qh[mt][kt] = g_qfrag[sb * 32 + lid];
            ql[mt][kt] = g_qfrag[(sb + 1) * 32 + lid];
        }

    asm volatile("cp.async.wait_group 2;" ::: "memory");
    __syncthreads();

    // ---- S = (Qh+Ql)@Kh  (bias preloaded) ----
    #pragma unroll
    for (int kt = 0; kt < 2; kt++) {
        const int dcol = h * 32 + kt * 16 + (grp & 1) * 8;
        #pragma unroll
        for (int ntp = 0; ntp < 4; ntp++) {
            const int mrow = ntp * 16 + lrow + (grp >> 1) * 8;
            uint32_t a = sKV + kv_off(mrow, dcol);
            uint32_t bh[4];
            ldsm_x4(bh, a);
            mma16816(sa[0][2*ntp],   (const uint32_t*)&qh[0][kt], bh);
            mma16816(sa[0][2*ntp+1], (const uint32_t*)&qh[0][kt], bh + 2);
            mma16816(sa[1][2*ntp],   (const uint32_t*)&qh[1][kt], bh);
            mma16816(sa[1][2*ntp+1], (const uint32_t*)&qh[1][kt], bh + 2);
            mma16816(sa[0][2*ntp],   (const uint32_t*)&ql[0][kt], bh);
            mma16816(sa[0][2*ntp+1], (const uint32_t*)&ql[0][kt], bh + 2);
            mma16816(sa[1][2*ntp],   (const uint32_t*)&ql[1][kt], bh);
            mma16816(sa[1][2*ntp+1], (const uint32_t*)&ql[1][kt], bh + 2);
        }
    }

    // ---- softmax ----
    float rinv[2][2];
    #pragma unroll
    for (int mt = 0; mt < 2; mt++)
        #pragma unroll
        for (int rh = 0; rh < 2; rh++) {
            float mx = -1e30f;
            #pragma unroll
            for (int nt = 0; nt < 8; nt++)
                mx = fmaxf(mx, fmaxf(sa[mt][nt][rh*2], sa[mt][nt][rh*2+1]));
            mx = fmaxf(mx, __shfl_xor_sync(0xffffffffu, mx, 1));
            mx = fmaxf(mx, __shfl_xor_sync(0xffffffffu, mx, 2));
            float ls = 0.f;
            #pragma unroll
            for (int nt = 0; nt < 8; nt++) {
                float p0 = __expf(sa[mt][nt][rh*2]   - mx);
                float p1 = __expf(sa[mt][nt][rh*2+1] - mx);
                sa[mt][nt][rh*2] = p0; sa[mt][nt][rh*2+1] = p1;
                ls += p0 + p1;
            }
            ls += __shfl_xor_sync(0xffffffffu, ls, 1);
            ls += __shfl_xor_sync(0xffffffffu, ls, 2);
            rinv[mt][rh] = 1.f / ls;
        }

    // ---- O = (Ph+Pl)@Vh ----
    float oa[2][4][4];
    #pragma unroll
    for (int mt = 0; mt < 2; mt++)
        #pragma unroll
        for (int nt = 0; nt < 4; nt++)
            #pragma unroll
            for (int i = 0; i < 4; i++) oa[mt][nt][i] = 0.f;

    #pragma unroll
    for (int j = 0; j < 4; j++) {
        uint32_t Ph[2][4], Pl[2][4];
        #pragma unroll
        for (int mt = 0; mt < 2; mt++) {
            Ph[mt][0] = split2h(sa[mt][2*j][0],   sa[mt][2*j][1],   Pl[mt][0]);
            Ph[mt][1] = split2h(sa[mt][2*j][2],   sa[mt][2*j][3],   Pl[mt][1]);
            Ph[mt][2] = split2h(sa[mt][2*j+1][0], sa[mt][2*j+1][1], Pl[mt][2]);
            Ph[mt][3] = split2h(sa[mt][2*j+1][2], sa[mt][2*j+1][3], Pl[mt][3]);
        }
        #pragma unroll
        for (int ep = 0; ep < 2; ep++) {
            const int mrow = j * 16 + lrow + (grp & 1) * 8;
            const int ecol = h * 32 + ep * 16 + (grp >> 1) * 8;
            uint32_t va = sKV + 32768 + kv_off(mrow, ecol);
            uint32_t vh[4];
            ldsm_x4_t(vh, va);
            #pragma unroll
            for (int mt = 0; mt < 2; mt++) {
                mma16816(oa[mt][2*ep],   Ph[mt], vh);
                mma16816(oa[mt][2*ep+1], Ph[mt], vh + 2);
                mma16816(oa[mt][2*ep],   Pl[mt], vh);
                mma16816(oa[mt][2*ep+1], Pl[mt], vh + 2);
            }
        }
    }

    // ---- stage O (scaled) into smem as fp16 hi only, 64-row SW128 layout ----
    __syncthreads();    // all K/V reads done; reuse sKV region for O
    const int q2 = (lid & 3) * 2, r4 = lid >> 2;
    char* sm = asmem + (sKV - sraw);
    #pragma unroll
    for (int mt = 0; mt < 2; mt++)
        #pragma unroll
        for (int rh = 0; rh < 2; rh++) {
            const int n = s * 32 + mt * 16 + r4 + rh * 8;
            const float sc = rinv[mt][rh];
            #pragma unroll
            for (int nt = 0; nt < 4; nt++) {
                const int col = h * 32 + nt * 8 + q2;
                *(uint32_t*)(sm + kv_off(n, col)) =
                    pack2h(oa[mt][nt][rh*2] * sc, oa[mt][nt][rh*2+1] * sc);
            }
        }
    asm volatile("cp.async.wait_group 0;" ::: "memory");
    __syncthreads();

    // ---- proj: C[64x256] = Oh @ PWh^T + proj_b (1 term, full unroll) ----
    const int mw = wid >> 2, nw = wid & 3;          // warp tile 16 rows x 64 cols
    const int arow = mw * 16 + lrow + (grp & 1) * 8;
    const int kqa = (grp >> 1) * 8;
    const int kqb = (grp & 1) * 8;
    int nrow[4];
    #pragma unroll
    for (int t = 0; t < 4; t++) nrow[t] = nw * 64 + t * 16 + lrow + (grp >> 1) * 8;
    const uint32_t sPw = sP + (uint32_t)(nw >> 1) * 65536;

    float pc[8][4];
    #pragma unroll
    for (int nt = 0; nt < 8; nt++)
        #pragma unroll
        for (int i = 0; i < 4; i++) pc[nt][i] = 0.f;

    #pragma unroll
    for (int ks = 0; ks < 16; ks++) {
        const int k = ks * 16;
        uint32_t ah[4], bb[4][4];
        ldsm_x4(ah, sKV + kv_off(arow, k + kqa));
        #pragma unroll
        for (int t = 0; t < 4; t++) {
            uint32_t ba = sPw + (uint32_t)((k + kqb) >> 7) * 32768
                        + a_sw_off(nrow[t] & 127, (k + kqb) & 127);
            ldsm_x4(bb[t], ba);
        }
        #pragma unroll
        for (int t = 0; t < 4; t++) {
            mma16816(pc[2*t],   ah, bb[t]);
            mma16816(pc[2*t+1], ah, bb[t] + 2);
        }
    }

    // ---- epilogue: bias + store out ----
    float* obase = out + (size_t)blockIdx.x * 64 * 256;
    #pragma unroll
    for (int nt = 0; nt < 8; nt++) {
        const int col = nw * 64 + nt * 8 + q2;
        const float2 bv = *(const float2*)(proj_b + col);
        const int rlo = mw * 16 + r4;
        *(float2*)(obase + (size_t)rlo * 256 + col) =
            make_float2(pc[nt][0] + bv.x, pc[nt][1] + bv.y);
        *(float2*)(obase + (size_t)(rlo + 8) * 256 + col) =
            make_float2(pc[nt][2] + bv.x, pc[nt][3] + bv.y);
    }
}

// ---------------- launcher ----------------
extern "C" void kernel_launch(void* const* d_in, const int* in_sizes, int n_in,
                              void* d_out, int out_size) {
    const float* x      = (const float*)d_in[0];
    const float* emb    = (const float*)d_in[1];
    const float* rpb    = (const float*)d_in[2];
    const float* q_w    = (const float*)d_in[3];
    const float* q_b    = (const float*)d_in[4];
    const float* kv_w   = (const float*)d_in[5];
    const float* kv_b   = (const float*)d_in[6];
    const float* proj_w = (const float*)d_in[7];
    const float* proj_b = (const float*)d_in[8];
    float* out = (float*)d_out;
    (void)in_sizes; (void)n_in; (void)out_size;

    const int GSM = 1024 + 65536 + 131072;   // 197632: pad + A + 4x32KB ring
    const int ASM = 1024 + 65536 + 131072;   // 197632: pad + KV + P

    cudaFuncSetAttribute(gemm_kernel,
                         cudaFuncAttributeMaxDynamicSharedMemorySize, GSM);
    cudaFuncSetAttribute(attn_kernel,
                         cudaFuncAttributeMaxDynamicSharedMemorySize, ASM);

    setup_kernel<<<480, 512>>>(emb, rpb, q_w, q_b, kv_w, proj_w);
    setup2_kernel<<<8, 512>>>();
    gemm_kernel<<<1024, 512, GSM>>>(x, kv_b);
    attn_kernel<<<2048, 512, ASM>>>(proj_b, out);
}